// round 9
// baseline (speedup 1.0000x reference)
#include <cuda_runtime.h>
#include <cuda_bf16.h>

// Problem constants (B=256 rows, D=512 cols, row-major [B, D])
#define B_ROWS 256
#define D_COLS 512
#define CPB 8                 // columns per block
#define GRID (D_COLS / CPB)   // 64 blocks (single wave)
#define THREADS 256
#define RPT (B_ROWS / (THREADS / CPB)) // 8 rows per thread

__global__ __launch_bounds__(THREADS) void kl_fused_kernel(
    const float* __restrict__ mu, const float* __restrict__ logvar,
    float* __restrict__ out)
{
    const int tid = threadIdx.x;
    const int c   = tid & (CPB - 1);       // column within this block's group
    const int rb  = tid >> 3;              // 0..31 row base
    const int d   = blockIdx.x * CPB + c;  // global column

    // ---- Phase 1: issue all loads up-front for max MLP ----
    float mv[RPT], lvv[RPT];
    #pragma unroll
    for (int k = 0; k < RPT; k++) {
        const int i = rb + k * 32;
        mv[k]  = mu[i * D_COLS + d];
        lvv[k] = logvar[i * D_COLS + d];
    }

    // 5 fused stats: s03 = var + mu^2, s1 = 1/var, s2 = mu,
    //                s4 = mu/var,      s5 = mu^2/var
    float s03 = 0.f, s1 = 0.f, s2 = 0.f, s4 = 0.f, s5 = 0.f;
    #pragma unroll
    for (int k = 0; k < RPT; k++) {
        const float m  = mv[k];
        const float v  = __expf(lvv[k]);
        const float iv = __expf(-lvv[k]);
        s03 += v + m * m;
        s1  += iv;
        s2  += m;
        s4  += m * iv;
        s5  += m * m * iv;
    }

    // ---- Warp reduce across row-groups: lanes {c, c+8, c+16, c+24} ----
    #pragma unroll
    for (int off = 16; off >= 8; off >>= 1) {
        s03 += __shfl_down_sync(0xFFFFFFFFu, s03, off);
        s1  += __shfl_down_sync(0xFFFFFFFFu, s1,  off);
        s2  += __shfl_down_sync(0xFFFFFFFFu, s2,  off);
        s4  += __shfl_down_sync(0xFFFFFFFFu, s4,  off);
        s5  += __shfl_down_sync(0xFFFFFFFFu, s5,  off);
    }

    __shared__ float sh[5][8][CPB];   // [stat][warp][col]
    const int warp = tid >> 5;
    const int lane = tid & 31;
    if (lane < CPB) {
        sh[0][warp][lane] = s03; sh[1][warp][lane] = s1; sh[2][warp][lane] = s2;
        sh[3][warp][lane] = s4;  sh[4][warp][lane] = s5;
    }
    __syncthreads();

    // ---- Threads 0..7: combine 8 warps for one column each ----
    float blk = 0.0f;
    if (tid < CPB) {
        float t03 = 0.f, t1 = 0.f, t2 = 0.f, t4 = 0.f, t5 = 0.f;
        #pragma unroll
        for (int w = 0; w < 8; w++) {
            t03 += sh[0][w][tid]; t1 += sh[1][w][tid]; t2 += sh[2][w][tid];
            t4  += sh[3][w][tid]; t5 += sh[4][w][tid];
        }
        const float Bf = (float)B_ROWS;
        // c_d = S_inv*(S_var + S_mu2) - 2*S_mu*S_muinv + B*S_mu2inv - B^2
        blk = t1 * t03 - 2.0f * t2 * t4 + Bf * t5 - Bf * Bf;
    }

    // ---- Tail: 8 col contributions -> 1 scalar -> ONE fire-and-forget red ----
    if (warp == 0) {
        blk += __shfl_down_sync(0xFFFFFFFFu, blk, 4);
        blk += __shfl_down_sync(0xFFFFFFFFu, blk, 2);
        blk += __shfl_down_sync(0xFFFFFFFFu, blk, 1);
        if (lane == 0) {
            const float scaled = blk * (0.5f / (float)B_ROWS);
            // No-return reduction into out[0] (zeroed by the memset node).
            asm volatile("red.relaxed.gpu.global.add.f32 [%0], %1;"
                         :: "l"(out), "f"(scaled) : "memory");
        }
    }
}

extern "C" void kernel_launch(void* const* d_in, const int* in_sizes, int n_in,
                              void* d_out, int out_size)
{
    const float* mu = (const float*)d_in[0];
    const float* lv = (const float*)d_in[1];
    float* out = (float*)d_out;

    // Graph-capturable memset node: zero the 4-byte accumulator each replay.
    cudaMemsetAsync(d_out, 0, sizeof(float), 0);
    kl_fused_kernel<<<GRID, THREADS>>>(mu, lv, out);
}

// round 10
// speedup vs baseline: 1.0741x; 1.0741x over previous
#include <cuda_runtime.h>
#include <cuda_bf16.h>

// Problem constants (B=256 rows, D=512 cols, row-major [B, D])
#define B_ROWS 256
#define D_COLS 512
#define CPB 8                 // columns per block
#define GRID (D_COLS / CPB)   // 64 blocks (single wave)
#define THREADS 256
#define RPT (B_ROWS / (THREADS / CPB)) // 8 rows per thread

// Fixed-point accumulator packing:
//   bits [0,52):  biased fixed-point sum (each block adds q = round(blk*2^20) + 2^44 > 0)
//   bits [52,..): arrival count (each block adds 1<<52)
#define FP_SCALE 1048576.0f          // 2^20
#define FP_BIAS  (1LL << 44)
#define CNT_SHIFT 52
#define SUM_MASK ((1ULL << CNT_SHIFT) - 1ULL)

// Scratch (no device allocation allowed); reset by last block each replay.
__device__ unsigned long long g_pack = 0ULL;

__global__ __launch_bounds__(THREADS) void kl_fused_kernel(
    const float* __restrict__ mu, const float* __restrict__ logvar,
    float* __restrict__ out)
{
    const int tid = threadIdx.x;
    const int c   = tid & (CPB - 1);       // column within this block's group
    const int rb  = tid >> 3;              // 0..31 row base
    const int d   = blockIdx.x * CPB + c;  // global column

    // ---- Phase 1: issue all loads up-front for max MLP ----
    float mv[RPT], lvv[RPT];
    #pragma unroll
    for (int k = 0; k < RPT; k++) {
        const int i = rb + k * 32;
        mv[k]  = mu[i * D_COLS + d];
        lvv[k] = logvar[i * D_COLS + d];
    }

    // 5 fused stats: s03 = var + mu^2, s1 = 1/var, s2 = mu,
    //                s4 = mu/var,      s5 = mu^2/var
    float s03 = 0.f, s1 = 0.f, s2 = 0.f, s4 = 0.f, s5 = 0.f;
    #pragma unroll
    for (int k = 0; k < RPT; k++) {
        const float m  = mv[k];
        const float v  = __expf(lvv[k]);
        const float iv = __expf(-lvv[k]);
        s03 += v + m * m;
        s1  += iv;
        s2  += m;
        s4  += m * iv;
        s5  += m * m * iv;
    }

    // ---- Warp reduce across row-groups: lanes {c, c+8, c+16, c+24} ----
    #pragma unroll
    for (int off = 16; off >= 8; off >>= 1) {
        s03 += __shfl_down_sync(0xFFFFFFFFu, s03, off);
        s1  += __shfl_down_sync(0xFFFFFFFFu, s1,  off);
        s2  += __shfl_down_sync(0xFFFFFFFFu, s2,  off);
        s4  += __shfl_down_sync(0xFFFFFFFFu, s4,  off);
        s5  += __shfl_down_sync(0xFFFFFFFFu, s5,  off);
    }

    __shared__ float sh[5][8][CPB];   // [stat][warp][col]
    const int warp = tid >> 5;
    const int lane = tid & 31;
    if (lane < CPB) {
        sh[0][warp][lane] = s03; sh[1][warp][lane] = s1; sh[2][warp][lane] = s2;
        sh[3][warp][lane] = s4;  sh[4][warp][lane] = s5;
    }
    __syncthreads();

    // ---- Threads 0..7: combine 8 warps for one column each ----
    float blk = 0.0f;
    if (tid < CPB) {
        float t03 = 0.f, t1 = 0.f, t2 = 0.f, t4 = 0.f, t5 = 0.f;
        #pragma unroll
        for (int w = 0; w < 8; w++) {
            t03 += sh[0][w][tid]; t1 += sh[1][w][tid]; t2 += sh[2][w][tid];
            t4  += sh[3][w][tid]; t5 += sh[4][w][tid];
        }
        const float Bf = (float)B_ROWS;
        // c_d = S_inv*(S_var + S_mu2) - 2*S_mu*S_muinv + B*S_mu2inv - B^2
        blk = t1 * t03 - 2.0f * t2 * t4 + Bf * t5 - Bf * Bf;
    }

    // ---- Tail: one packed u64 atomic per block; last arriver finalizes ----
    if (warp == 0) {
        blk += __shfl_down_sync(0xFFFFFFFFu, blk, 4);
        blk += __shfl_down_sync(0xFFFFFFFFu, blk, 2);
        blk += __shfl_down_sync(0xFFFFFFFFu, blk, 1);
        if (lane == 0) {
            const long long q = llrintf(blk * FP_SCALE) + FP_BIAS; // always > 0
            const unsigned long long add =
                (1ULL << CNT_SHIFT) + (unsigned long long)q;
            const unsigned long long prev = atomicAdd(&g_pack, add);
            if ((prev >> CNT_SHIFT) == GRID - 1) {
                // I'm the last arriver: prev+add holds the complete packed sum.
                const long long total_fixed =
                    (long long)((prev + add) & SUM_MASK)
                    - (long long)GRID * FP_BIAS;
                const double total = (double)total_fixed
                    * (0.5 / ((double)B_ROWS * (double)FP_SCALE));
                out[0] = (float)total;
                g_pack = 0ULL;  // reset for next graph replay
            }
        }
    }
}

extern "C" void kernel_launch(void* const* d_in, const int* in_sizes, int n_in,
                              void* d_out, int out_size)
{
    const float* mu = (const float*)d_in[0];
    const float* lv = (const float*)d_in[1];
    float* out = (float*)d_out;

    kl_fused_kernel<<<GRID, THREADS>>>(mu, lv, out);
}

// round 11
// speedup vs baseline: 1.1208x; 1.0435x over previous
#include <cuda_runtime.h>
#include <cuda_bf16.h>

// Problem constants (B=256 rows, D=512 cols, row-major [B, D])
#define B_ROWS 256
#define D_COLS 512
#define CPB 8                 // columns per block
#define GRID (D_COLS / CPB)   // 64 blocks (single wave)
#define THREADS 256
#define RPT (B_ROWS / (THREADS / CPB)) // 8 rows per thread

// Fixed-point accumulator packing:
//   bits [0,52):  biased fixed-point sum (each block adds q = round(blk*2^20) + 2^44 > 0)
//   bits [52,..): arrival count (each block adds 1<<52)
#define FP_SCALE 1048576.0f          // 2^20
#define FP_BIAS  (1LL << 44)
#define CNT_SHIFT 52
#define SUM_MASK ((1ULL << CNT_SHIFT) - 1ULL)

// Scratch (no device allocation allowed); reset by finalizer each replay.
__device__ unsigned long long g_pack  = 0ULL;
__device__ unsigned int       g_start = 0u;

__global__ __launch_bounds__(THREADS) void kl_fused_kernel(
    const float* __restrict__ mu, const float* __restrict__ logvar,
    float* __restrict__ out)
{
    const int tid = threadIdx.x;

    // ---- Finalizer designation at START: return latency hides under body ----
    unsigned int start_prev = 0u;
    if (tid == 0) start_prev = atomicAdd(&g_start, 1u);

    const int c   = tid & (CPB - 1);       // column within this block's group
    const int rb  = tid >> 3;              // 0..31 row base
    const int d   = blockIdx.x * CPB + c;  // global column

    // ---- Phase 1: issue all loads up-front for max MLP ----
    float mv[RPT], lvv[RPT];
    #pragma unroll
    for (int k = 0; k < RPT; k++) {
        const int i = rb + k * 32;
        mv[k]  = mu[i * D_COLS + d];
        lvv[k] = logvar[i * D_COLS + d];
    }

    // 5 fused stats: s03 = var + mu^2, s1 = 1/var, s2 = mu,
    //                s4 = mu/var,      s5 = mu^2/var
    float s03 = 0.f, s1 = 0.f, s2 = 0.f, s4 = 0.f, s5 = 0.f;
    #pragma unroll
    for (int k = 0; k < RPT; k++) {
        const float m  = mv[k];
        const float v  = __expf(lvv[k]);
        const float iv = __expf(-lvv[k]);
        s03 += v + m * m;
        s1  += iv;
        s2  += m;
        s4  += m * iv;
        s5  += m * m * iv;
    }

    // ---- Warp reduce across row-groups: lanes {c, c+8, c+16, c+24} ----
    #pragma unroll
    for (int off = 16; off >= 8; off >>= 1) {
        s03 += __shfl_down_sync(0xFFFFFFFFu, s03, off);
        s1  += __shfl_down_sync(0xFFFFFFFFu, s1,  off);
        s2  += __shfl_down_sync(0xFFFFFFFFu, s2,  off);
        s4  += __shfl_down_sync(0xFFFFFFFFu, s4,  off);
        s5  += __shfl_down_sync(0xFFFFFFFFu, s5,  off);
    }

    __shared__ float sh[5][8][CPB];   // [stat][warp][col]
    const int warp = tid >> 5;
    const int lane = tid & 31;
    if (lane < CPB) {
        sh[0][warp][lane] = s03; sh[1][warp][lane] = s1; sh[2][warp][lane] = s2;
        sh[3][warp][lane] = s4;  sh[4][warp][lane] = s5;
    }
    __syncthreads();

    // ---- Threads 0..7: combine 8 warps for one column each ----
    float blk = 0.0f;
    if (tid < CPB) {
        float t03 = 0.f, t1 = 0.f, t2 = 0.f, t4 = 0.f, t5 = 0.f;
        #pragma unroll
        for (int w = 0; w < 8; w++) {
            t03 += sh[0][w][tid]; t1 += sh[1][w][tid]; t2 += sh[2][w][tid];
            t4  += sh[3][w][tid]; t5 += sh[4][w][tid];
        }
        const float Bf = (float)B_ROWS;
        // c_d = S_inv*(S_var + S_mu2) - 2*S_mu*S_muinv + B*S_mu2inv - B^2
        blk = t1 * t03 - 2.0f * t2 * t4 + Bf * t5 - Bf * Bf;
    }

    // ---- Tail: fire-and-forget packed red; only the finalizer waits ----
    if (warp == 0) {
        blk += __shfl_down_sync(0xFFFFFFFFu, blk, 4);
        blk += __shfl_down_sync(0xFFFFFFFFu, blk, 2);
        blk += __shfl_down_sync(0xFFFFFFFFu, blk, 1);
        if (lane == 0) {
            const long long q = llrintf(blk * FP_SCALE) + FP_BIAS; // always > 0
            const unsigned long long add =
                (1ULL << CNT_SHIFT) + (unsigned long long)q;
            // No-return reduction: 63 blocks exit right after issuing this.
            asm volatile("red.relaxed.gpu.global.add.u64 [%0], %1;"
                         :: "l"(&g_pack), "l"(add) : "memory");

            if (start_prev == GRID - 1) {
                // Last starter finalizes: poll until all 64 reds landed.
                unsigned long long p;
                do {
                    asm volatile("ld.relaxed.gpu.global.u64 %0, [%1];"
                                 : "=l"(p) : "l"(&g_pack) : "memory");
                } while ((p >> CNT_SHIFT) != (unsigned long long)GRID);

                const long long total_fixed =
                    (long long)(p & SUM_MASK) - (long long)GRID * FP_BIAS;
                const double total = (double)total_fixed
                    * (0.5 / ((double)B_ROWS * (double)FP_SCALE));
                out[0] = (float)total;
                // Reset scratch for next graph replay.
                g_pack  = 0ULL;
                g_start = 0u;
            }
        }
    }
}

extern "C" void kernel_launch(void* const* d_in, const int* in_sizes, int n_in,
                              void* d_out, int out_size)
{
    const float* mu = (const float*)d_in[0];
    const float* lv = (const float*)d_in[1];
    float* out = (float*)d_out;

    kl_fused_kernel<<<GRID, THREADS>>>(mu, lv, out);
}